// round 1
// baseline (speedup 1.0000x reference)
#include <cuda_runtime.h>
#include <cuda_bf16.h>
#include <math.h>

#define T_TOK 8192
#define HID   7168
#define NEXP  256

// ---- scratch: sigmoid scores [T_TOK, NEXP] (8 MB, static device array) ----
__device__ float g_scores[(size_t)T_TOK * NEXP];

// ============================================================================
// Kernel 1: scores = sigmoid(x @ W^T)   (fp32 SIMT GEMM, NT layout)
//   CTA tile 128x128, BK=16, 256 threads, 8x8 per-thread microtile
// ============================================================================
constexpr int BM = 128, BN = 128, BK = 16;

__global__ __launch_bounds__(256) void gemm_sigmoid_kernel(
    const float* __restrict__ x,   // [T_TOK, HID]
    const float* __restrict__ w)   // [NEXP, HID]
{
    __shared__ float As[BK][BM];
    __shared__ float Bs[BK][BN];

    const int tid = threadIdx.x;
    const int m0 = blockIdx.y * BM;
    const int n0 = blockIdx.x * BN;

    // global-load mapping: each thread loads 2 float4 per tile per operand
    const int arow = tid >> 1;          // 0..127
    const int akq  = (tid & 1) * 2;     // float4 index within the 16-wide k slab: akq, akq+1
    const float4* xg = (const float4*)(x + (size_t)(m0 + arow) * HID);
    const float4* wg = (const float4*)(w + (size_t)(n0 + arow) * HID);

    // compute mapping: 16x16 thread grid, 8x8 microtile
    const int tm = (tid >> 4) << 3;
    const int tn = (tid & 15) << 3;

    float acc[8][8];
#pragma unroll
    for (int i = 0; i < 8; ++i)
#pragma unroll
        for (int j = 0; j < 8; ++j) acc[i][j] = 0.f;

    const int KT = HID / BK;   // 448
    float4 pa0 = xg[akq], pa1 = xg[akq + 1];
    float4 pb0 = wg[akq], pb1 = wg[akq + 1];

    for (int kt = 0; kt < KT; ++kt) {
        const int kb = akq * 4;
        As[kb + 0][arow] = pa0.x; As[kb + 1][arow] = pa0.y;
        As[kb + 2][arow] = pa0.z; As[kb + 3][arow] = pa0.w;
        As[kb + 4][arow] = pa1.x; As[kb + 5][arow] = pa1.y;
        As[kb + 6][arow] = pa1.z; As[kb + 7][arow] = pa1.w;
        Bs[kb + 0][arow] = pb0.x; Bs[kb + 1][arow] = pb0.y;
        Bs[kb + 2][arow] = pb0.z; Bs[kb + 3][arow] = pb0.w;
        Bs[kb + 4][arow] = pb1.x; Bs[kb + 5][arow] = pb1.y;
        Bs[kb + 6][arow] = pb1.z; Bs[kb + 7][arow] = pb1.w;
        __syncthreads();

        if (kt + 1 < KT) {
            const int nb = (kt + 1) * 4;
            pa0 = xg[nb + akq]; pa1 = xg[nb + akq + 1];
            pb0 = wg[nb + akq]; pb1 = wg[nb + akq + 1];
        }

#pragma unroll
        for (int kk = 0; kk < BK; ++kk) {
            float a[8], b[8];
            *(float4*)(a + 0) = *(const float4*)&As[kk][tm];
            *(float4*)(a + 4) = *(const float4*)&As[kk][tm + 4];
            *(float4*)(b + 0) = *(const float4*)&Bs[kk][tn];
            *(float4*)(b + 4) = *(const float4*)&Bs[kk][tn + 4];
#pragma unroll
            for (int i = 0; i < 8; ++i)
#pragma unroll
                for (int j = 0; j < 8; ++j)
                    acc[i][j] = fmaf(a[i], b[j], acc[i][j]);
        }
        __syncthreads();
    }

    // epilogue: sigmoid, store to scratch
#pragma unroll
    for (int i = 0; i < 8; ++i) {
        float* orow = g_scores + (size_t)(m0 + tm + i) * NEXP + n0 + tn;
#pragma unroll
        for (int j = 0; j < 8; ++j) {
            float v = acc[i][j];
            orow[j] = 1.f / (1.f + expf(-v));
        }
    }
}

// ============================================================================
// Kernel 2: grouped top-k routing. One block (256 threads) per token.
//   group g = experts [32g, 32g+32)  == warp g of the block
//   group_score = sum of top-2 (scores + bias) within group
//   keep top-4 groups, top-8 experts over kept groups (jax tie-break: lower idx)
//   weights = original sigmoid scores at chosen idx, normalized, * 2.5
// ============================================================================
__global__ __launch_bounds__(256) void gate_topk_kernel(
    const float* __restrict__ bias,
    float* __restrict__ out, int out_size)
{
    const int t   = blockIdx.x;
    const int tid = threadIdx.x;     // == expert id
    const int lane = tid & 31;
    const int grp  = tid >> 5;

    __shared__ float s_orig[NEXP];
    __shared__ float gsc[8];
    __shared__ int   keepm[8];
    __shared__ float rv[NEXP];
    __shared__ int   ri[NEXP];
    __shared__ int   selidx[8];

    const float s = g_scores[(size_t)t * NEXP + tid];
    const float v = s + bias[tid];           // scores_for_choice
    s_orig[tid] = s;

    // ---- per-group top-2 sum (warp == group of 32 experts) ----
    float m1 = v;
#pragma unroll
    for (int o = 16; o > 0; o >>= 1)
        m1 = fmaxf(m1, __shfl_xor_sync(0xffffffffu, m1, o));
    unsigned bal = __ballot_sync(0xffffffffu, v == m1);
    int fl = __ffs(bal) - 1;                 // first lane achieving max
    float v2 = (lane == fl) ? -INFINITY : v;
    float m2 = v2;
#pragma unroll
    for (int o = 16; o > 0; o >>= 1)
        m2 = fmaxf(m2, __shfl_xor_sync(0xffffffffu, m2, o));
    if (lane == 0) gsc[grp] = m1 + m2;
    __syncthreads();

    // ---- top-4 groups (serial on thread 0; lower index wins ties) ----
    if (tid == 0) {
        bool k[8];
#pragma unroll
        for (int g = 0; g < 8; ++g) k[g] = false;
        for (int r = 0; r < 4; ++r) {
            float best = -INFINITY; int bi = -1;
            for (int g = 0; g < 8; ++g)
                if (!k[g] && gsc[g] > best) { best = gsc[g]; bi = g; }
            k[bi] = true;
        }
#pragma unroll
        for (int g = 0; g < 8; ++g) keepm[g] = k[g] ? 1 : 0;
    }
    __syncthreads();

    float myv = keepm[grp] ? v : -INFINITY;

    // ---- iterative top-8 block argmax (descending, lower idx on ties) ----
    for (int r = 0; r < 8; ++r) {
        rv[tid] = myv; ri[tid] = tid;
        __syncthreads();
        for (int st = 128; st > 0; st >>= 1) {
            if (tid < st) {
                float a = rv[tid], b = rv[tid + st];
                int   ia = ri[tid], ib = ri[tid + st];
                if (b > a || (b == a && ib < ia)) { rv[tid] = b; ri[tid] = ib; }
            }
            __syncthreads();
        }
        const int win = ri[0];
        if (tid == 0) selidx[r] = win;
        __syncthreads();
        if (tid == win) myv = -INFINITY;
    }

    // ---- weights + output ----
    if (tid == 0) {
        float wv[8], sw = 0.f;
#pragma unroll
        for (int r = 0; r < 8; ++r) { wv[r] = s_orig[selidx[r]]; sw += wv[r]; }
        const float inv = 2.5f / (sw + 1e-20f);
        float* wout = out + (size_t)t * 8;
#pragma unroll
        for (int r = 0; r < 8; ++r) wout[r] = wv[r] * inv;
        if (out_size >= 2 * T_TOK * 8) {
            float* iout = out + (size_t)T_TOK * 8 + (size_t)t * 8;
#pragma unroll
            for (int r = 0; r < 8; ++r) iout[r] = (float)selidx[r];
        }
    }
}

// ============================================================================
extern "C" void kernel_launch(void* const* d_in, const int* in_sizes, int n_in,
                              void* d_out, int out_size)
{
    const float* x = nullptr; const float* w = nullptr; const float* b = nullptr;
    for (int i = 0; i < n_in; ++i) {
        long long sz = in_sizes[i];
        if (sz == (long long)T_TOK * HID) x = (const float*)d_in[i];
        else if (sz == (long long)NEXP * HID) w = (const float*)d_in[i];
        else if (sz == NEXP) b = (const float*)d_in[i];
    }
    float* out = (float*)d_out;

    dim3 grid(NEXP / BN, T_TOK / BM);   // (2, 64)
    gemm_sigmoid_kernel<<<grid, 256>>>(x, w);
    gate_topk_kernel<<<T_TOK, 256>>>(b, out, out_size);
}

// round 7
// speedup vs baseline: 1.0338x; 1.0338x over previous
#include <cuda_runtime.h>
#include <math.h>
#include <stdint.h>

#define T_TOK 8192
#define HID   7168
#define NEXP  256

// scratch: sigmoid scores [T_TOK, NEXP] (8 MB)
__device__ float g_scores[(size_t)T_TOK * NEXP];

// ============================ f32x2 helpers ============================
__device__ __forceinline__ unsigned long long pack2(float x) {
    unsigned long long r;
    asm("mov.b64 %0, {%1, %1};" : "=l"(r) : "f"(x));
    return r;
}
__device__ __forceinline__ void ffma2(unsigned long long& d,
                                      unsigned long long a,
                                      unsigned long long b) {
    asm("fma.rn.f32x2 %0, %1, %2, %0;" : "+l"(d) : "l"(a), "l"(b));
}
__device__ __forceinline__ float2 unpack2(unsigned long long v) {
    float2 f;
    asm("mov.b64 {%0, %1}, %2;" : "=f"(f.x), "=f"(f.y) : "l"(v));
    return f;
}

// ============================ GEMM config ============================
constexpr int BM = 128, BN = 128, BK = 16;
constexpr int KT = HID / BK;   // 448

// ============================================================================
// Kernel 1: scores = sigmoid(x @ W^T)
//   Numerics: per output element, fp32 FMA over k ascending (bit-identical to
//   the R1 SIMT kernel that passed) — packed two-at-a-time via fma.rn.f32x2.
//   128 threads, CTA tile 128x128, microtile 8m x 16n.
// ============================================================================
__global__ __launch_bounds__(128) void gemm_f32x2_kernel(
    const float* __restrict__ x,   // [T_TOK, HID]
    const float* __restrict__ w)   // [NEXP, HID]
{
    __shared__ float As[BK][BM];
    __shared__ float Bs[BK][BN];

    const int tid = threadIdx.x;
    const int n0 = (blockIdx.x & 1) * BN;
    const int m0 = (blockIdx.x >> 1) * BM;

    const int u = tid >> 3;   // 0..15  (m-group)
    const int v = tid & 7;    // 0..7   (n-group)

    // global load: thread t owns row t of both tiles, 16-k slab per chunk
    const float* ga = x + (size_t)(m0 + tid) * HID;
    const float* gb = w + (size_t)(n0 + tid) * HID;

    // acc[i][q][h]: rows {4u+i | i<4} U {64+4u+i-4 | i>=4},
    //              col pair = 4v + 32q + 2h .. +1
    unsigned long long acc[8][4][2];
#pragma unroll
    for (int i = 0; i < 8; ++i)
#pragma unroll
        for (int q = 0; q < 4; ++q)
#pragma unroll
            for (int h = 0; h < 2; ++h) acc[i][q][h] = 0ull;

    float4 pa[4], pb[4];
#pragma unroll
    for (int q = 0; q < 4; ++q) {
        pa[q] = *(const float4*)(ga + q * 4);
        pb[q] = *(const float4*)(gb + q * 4);
    }

#pragma unroll 1
    for (int kt = 0; kt < KT; ++kt) {
        // store chunk kt transposed into k-major smem
#pragma unroll
        for (int q = 0; q < 4; ++q) {
            As[q * 4 + 0][tid] = pa[q].x;
            As[q * 4 + 1][tid] = pa[q].y;
            As[q * 4 + 2][tid] = pa[q].z;
            As[q * 4 + 3][tid] = pa[q].w;
            Bs[q * 4 + 0][tid] = pb[q].x;
            Bs[q * 4 + 1][tid] = pb[q].y;
            Bs[q * 4 + 2][tid] = pb[q].z;
            Bs[q * 4 + 3][tid] = pb[q].w;
        }
        __syncthreads();

        if (kt + 1 < KT) {
            const float* na = ga + (kt + 1) * BK;
            const float* nb = gb + (kt + 1) * BK;
#pragma unroll
            for (int q = 0; q < 4; ++q) {
                pa[q] = *(const float4*)(na + q * 4);
                pb[q] = *(const float4*)(nb + q * 4);
            }
        }

#pragma unroll
        for (int kk = 0; kk < BK; ++kk) {
            // a fragment: 8 rows (broadcast across v-octets; conflict-free)
            float4 a0 = *(const float4*)&As[kk][4 * u];
            float4 a1 = *(const float4*)&As[kk][64 + 4 * u];
            unsigned long long a2[8];
            a2[0] = pack2(a0.x); a2[1] = pack2(a0.y);
            a2[2] = pack2(a0.z); a2[3] = pack2(a0.w);
            a2[4] = pack2(a1.x); a2[5] = pack2(a1.y);
            a2[6] = pack2(a1.z); a2[7] = pack2(a1.w);

            // b fragment: 4 quads of 4 cols, 32 apart (conflict-free)
            ulonglong2 bq[4];
#pragma unroll
            for (int q = 0; q < 4; ++q)
                bq[q] = *(const ulonglong2*)&Bs[kk][4 * v + 32 * q];

#pragma unroll
            for (int i = 0; i < 8; ++i)
#pragma unroll
                for (int q = 0; q < 4; ++q) {
                    ffma2(acc[i][q][0], a2[i], bq[q].x);
                    ffma2(acc[i][q][1], a2[i], bq[q].y);
                }
        }
        __syncthreads();
    }

    // epilogue: sigmoid + store
#pragma unroll
    for (int i = 0; i < 8; ++i) {
        const int row = m0 + ((i < 4) ? (4 * u + i) : (64 + 4 * u + i - 4));
        float* orow = g_scores + (size_t)row * NEXP + n0;
#pragma unroll
        for (int q = 0; q < 4; ++q) {
            float2 f0 = unpack2(acc[i][q][0]);
            float2 f1 = unpack2(acc[i][q][1]);
            float4 o;
            o.x = 1.f / (1.f + expf(-f0.x));
            o.y = 1.f / (1.f + expf(-f0.y));
            o.z = 1.f / (1.f + expf(-f1.x));
            o.w = 1.f / (1.f + expf(-f1.y));
            *(float4*)(orow + 4 * v + 32 * q) = o;
        }
    }
}

// ============================================================================
// Kernel 2: grouped top-k routing, one WARP per token (shuffles only)
//   (proven equivalent to the R1 block gate by the R5/R6 differential)
// ============================================================================
__global__ __launch_bounds__(256) void gate_warp_kernel(
    const float* __restrict__ bias,
    float* __restrict__ out, int out_size)
{
    const int wid = threadIdx.x >> 5;
    const int l   = threadIdx.x & 31;
    const int t   = blockIdx.x * 8 + wid;

    const float* srow = g_scores + (size_t)t * NEXP;
    float v[8];
#pragma unroll
    for (int k = 0; k < 8; ++k)
        v[k] = srow[k * 32 + l] + bias[k * 32 + l];

    // ---- per-group top-2 sum ----
    float gsc[8];
#pragma unroll
    for (int k = 0; k < 8; ++k) {
        float m1 = v[k];
#pragma unroll
        for (int o = 16; o > 0; o >>= 1) m1 = fmaxf(m1, __shfl_xor_sync(0xffffffffu, m1, o));
        unsigned bal = __ballot_sync(0xffffffffu, v[k] == m1);
        int fl = __ffs(bal) - 1;
        float vx = (l == fl) ? -INFINITY : v[k];
#pragma unroll
        for (int o = 16; o > 0; o >>= 1) vx = fmaxf(vx, __shfl_xor_sync(0xffffffffu, vx, o));
        gsc[k] = m1 + vx;
    }

    // ---- top-4 groups (strict > => lower idx wins ties) ----
    unsigned keep = 0;
#pragma unroll
    for (int r = 0; r < 4; ++r) {
        float best = -INFINITY; int bi = 0;
#pragma unroll
        for (int k = 0; k < 8; ++k) {
            bool tk = !((keep >> k) & 1u) && (gsc[k] > best);
            best = tk ? gsc[k] : best;
            bi   = tk ? k : bi;
        }
        keep |= 1u << bi;
    }

    float cand[8];
#pragma unroll
    for (int k = 0; k < 8; ++k) cand[k] = ((keep >> k) & 1u) ? v[k] : -INFINITY;

    // ---- top-8 experts (jax tie-break: lower expert idx) ----
    int sel[8];
#pragma unroll
    for (int r = 0; r < 8; ++r) {
        float bv = cand[0]; int bk = 0;
#pragma unroll
        for (int k = 1; k < 8; ++k) {
            bool tk = cand[k] > bv;
            bv = tk ? cand[k] : bv;
            bk = tk ? k : bk;
        }
        int be = bk * 32 + l;
#pragma unroll
        for (int o = 16; o > 0; o >>= 1) {
            float ov = __shfl_xor_sync(0xffffffffu, bv, o);
            int   oe = __shfl_xor_sync(0xffffffffu, be, o);
            if (ov > bv || (ov == bv && oe < be)) { bv = ov; be = oe; }
        }
        sel[r] = be;
        const int kk = be >> 5, ll = be & 31;
#pragma unroll
        for (int k = 0; k < 8; ++k)
            if (k == kk && l == ll) cand[k] = -INFINITY;
    }

    if (l == 0) {
        float wv[8], sw = 0.f;
#pragma unroll
        for (int r = 0; r < 8; ++r) { wv[r] = srow[sel[r]]; sw += wv[r]; }
        const float inv = 2.5f / (sw + 1e-20f);
        float4 w0 = make_float4(wv[0] * inv, wv[1] * inv, wv[2] * inv, wv[3] * inv);
        float4 w1 = make_float4(wv[4] * inv, wv[5] * inv, wv[6] * inv, wv[7] * inv);
        float4* wo = (float4*)(out + (size_t)t * 8);
        wo[0] = w0; wo[1] = w1;
        if (out_size >= 2 * T_TOK * 8) {
            float4 i0 = make_float4((float)sel[0], (float)sel[1], (float)sel[2], (float)sel[3]);
            float4 i1 = make_float4((float)sel[4], (float)sel[5], (float)sel[6], (float)sel[7]);
            float4* io = (float4*)(out + (size_t)T_TOK * 8 + (size_t)t * 8);
            io[0] = i0; io[1] = i1;
        }
    }
}

// ============================================================================
extern "C" void kernel_launch(void* const* d_in, const int* in_sizes, int n_in,
                              void* d_out, int out_size)
{
    const float* x = nullptr; const float* w = nullptr; const float* b = nullptr;
    for (int i = 0; i < n_in; ++i) {
        long long sz = in_sizes[i];
        if (sz == (long long)T_TOK * HID) x = (const float*)d_in[i];
        else if (sz == (long long)NEXP * HID) w = (const float*)d_in[i];
        else if (sz == NEXP) b = (const float*)d_in[i];
    }
    float* out = (float*)d_out;

    gemm_f32x2_kernel<<<(T_TOK / BM) * (NEXP / BN), 128>>>(x, w);
    gate_warp_kernel<<<T_TOK / 8, 256>>>(b, out, out_size);
}